// round 14
// baseline (speedup 1.0000x reference)
#include <cuda_runtime.h>
#include <cstdint>

#define BB 8
#define SS 4096
#define DD 1024
#define MTOT (BB*SS)            // 32768
#define NELEM (MTOT*DD)
#define NK 1024

#define NCH 32
#define CHL 128                 // SS/NCH

// ---- GEMM tiling (256-thread CTA, warp tile 32x64) ----
#define TM 128
#define TKC 32
#define KT (NK/TKC)             // 32
#define STAGES 3
#define AST 36
#define BST 136
#define ABYT (TM*AST*4)         // 18432
#define BBYT (TKC*BST*4)        // 17408
#define STBYT (ABYT+BBYT)       // 35840
#define SMEM_REQ (STAGES*STBYT) // 107520

// ---------------- scratch ----------------
__device__ float g_xg[NELEM];   // gelu(x)
__device__ float g_u [NELEM];
__device__ float g_v [NELEM];
__device__ float g_gx[NELEM];   // scaled_in -> bwd states
__device__ float g_ga[NELEM];   // a (decay)
__device__ float g_wt[6*NK*NK]; // tf32-rounded weights [K][N]
__device__ float g_sp[DD];      // softplus(a_param)
__device__ float g_e1[BB*NCH*DD];
__device__ float g_P1[BB*NCH*DD];
__device__ float g_c1[BB*NCH*DD];
__device__ float g_e2[BB*NCH*DD];
__device__ float g_P2[BB*NCH*DD];
__device__ float g_c2[BB*NCH*DD];

// ---------------- helpers ----------------
__device__ __forceinline__ float to_tf32(float x) {
    float r; asm("cvt.rna.tf32.f32 %0, %1;" : "=f"(r) : "f"(x)); return r;
}
__device__ __forceinline__ uint32_t smem_u32(const void* p) {
    uint32_t a;
    asm("{ .reg .u64 t; cvta.to.shared.u64 t, %1; cvt.u32.u64 %0, t; }" : "=r"(a) : "l"(p));
    return a;
}
__device__ __forceinline__ void cp16(uint32_t saddr, const void* gaddr) {
    asm volatile("cp.async.cg.shared.global [%0], [%1], 16;" :: "r"(saddr), "l"(gaddr));
}
__device__ __forceinline__ void cp_commit() {
    asm volatile("cp.async.commit_group;" ::: "memory");
}
__device__ __forceinline__ void cp_wait1() {
    asm volatile("cp.async.wait_group 1;" ::: "memory");
}
__device__ __forceinline__ void mma_tf32(float4& c, const uint32_t* a, const uint32_t* b) {
    asm volatile(
        "mma.sync.aligned.m16n8k8.row.col.f32.tf32.tf32.f32 "
        "{%0,%1,%2,%3},{%4,%5,%6,%7},{%8,%9},{%0,%1,%2,%3};\n"
        : "+f"(c.x), "+f"(c.y), "+f"(c.z), "+f"(c.w)
        : "r"(a[0]), "r"(a[1]), "r"(a[2]), "r"(a[3]), "r"(b[0]), "r"(b[1]));
}
__device__ __forceinline__ float fast_sigmoid(float x) {
    return 1.0f / (1.0f + __expf(-x));
}

// ---------------- weight prep ----------------
__global__ void roundw_all(const float* __restrict__ w0, const float* __restrict__ w1,
                           const float* __restrict__ w2, const float* __restrict__ w3,
                           const float* __restrict__ w4, const float* __restrict__ w5,
                           float* __restrict__ dst) {
    const float* srcs[6] = {w0, w1, w2, w3, w4, w5};
    const float* src = srcs[blockIdx.y];
    float* d = dst + (size_t)blockIdx.y * NK * NK;
    int i = blockIdx.x * blockDim.x + threadIdx.x;
    float4 v = reinterpret_cast<const float4*>(src)[i];
    v.x = to_tf32(v.x); v.y = to_tf32(v.y); v.z = to_tf32(v.z); v.w = to_tf32(v.w);
    reinterpret_cast<float4*>(d)[i] = v;
}

__global__ void softplus_prep(const float* __restrict__ ap, float* __restrict__ sp) {
    int d = threadIdx.x;
    sp[d] = log1pf(expf(ap[d]));
}

// ---------------- gelu ----------------
__global__ void gelu_kernel(const float* __restrict__ x, float* __restrict__ y) {
    int i = blockIdx.x * blockDim.x + threadIdx.x;
    float4 v = reinterpret_cast<const float4*>(x)[i];
    float* p = &v.x;
    float4 r; float* q = &r.x;
#pragma unroll
    for (int k = 0; k < 4; ++k) {
        float t = p[k];
        float inner = 0.7978845608028654f * (t + 0.044715f * t * t * t);
        q[k] = to_tf32(t * fast_sigmoid(2.0f * inner));
    }
    reinterpret_cast<float4*>(y)[i] = r;
}

// ---------------- merged chunked scans ----------------
__global__ void scan_p1(const float* __restrict__ u, const float* __restrict__ afwd,
                        const float* __restrict__ s, const float* __restrict__ a,
                        float* __restrict__ e1, float* __restrict__ P1,
                        float* __restrict__ e2, float* __restrict__ P2) {
    int d = threadIdx.x, bc = blockIdx.x;
    size_t base = (size_t)bc * CHL * DD + d;
    if (blockIdx.y == 0) {
        float av = afwd[d];
        float h = 0.f;
#pragma unroll 4
        for (int t = 0; t < CHL; ++t) h = fmaf(av, h, u[base + (size_t)t * DD]);
        float p = av;
#pragma unroll
        for (int i = 0; i < 7; ++i) p *= p;     // a^128
        e1[bc * DD + d] = h; P1[bc * DD + d] = p;
    } else {
        float h = 0.f, p = 1.f;
#pragma unroll 4
        for (int t = CHL - 1; t >= 0; --t) {
            size_t i = base + (size_t)t * DD;
            float av = a[i];
            h = fmaf(av, h, s[i]);
            p *= av;
        }
        e2[bc * DD + d] = h; P2[bc * DD + d] = p;
    }
}

__global__ void scan_p2(const float* __restrict__ e1, const float* __restrict__ P1,
                        float* __restrict__ c1,
                        const float* __restrict__ e2, const float* __restrict__ P2,
                        float* __restrict__ c2) {
    int gidx = blockIdx.x * blockDim.x + threadIdx.x;
    int b = gidx >> 10, d = gidx & 1023;
    if (blockIdx.y == 0) {
        float acc = 0.f;
        for (int c = 0; c < NCH; ++c) {
            size_t i = (size_t)(b * NCH + c) * DD + d;
            c1[i] = acc;
            acc = e1[i] + P1[i] * acc;
        }
    } else {
        float acc = 0.f;
        for (int c = NCH - 1; c >= 0; --c) {
            size_t i = (size_t)(b * NCH + c) * DD + d;
            c2[i] = acc;
            acc = e2[i] + P2[i] * acc;
        }
    }
}

__global__ void scan_p3(float* __restrict__ u, const float* __restrict__ afwd,
                        const float* __restrict__ c1,
                        float* __restrict__ s, const float* __restrict__ a,
                        const float* __restrict__ c2) {
    int d = threadIdx.x, bc = blockIdx.x;
    size_t base = (size_t)bc * CHL * DD + d;
    if (blockIdx.y == 0) {
        float av = afwd[d];
        float h = c1[bc * DD + d];
#pragma unroll 4
        for (int t = 0; t < CHL; ++t) {
            size_t i = base + (size_t)t * DD;
            h = fmaf(av, h, u[i]);
            u[i] = to_tf32(h);
        }
    } else {
        float h = c2[bc * DD + d];
#pragma unroll 4
        for (int t = CHL - 1; t >= 0; --t) {
            size_t i = base + (size_t)t * DD;
            h = fmaf(a[i], h, s[i]);
            s[i] = to_tf32(h);
        }
    }
}

// fragment-load macros (shared by all GEMM mainloops)
#define LOAD_AF(dst, aR, kk)                                          \
    do {                                                              \
        _Pragma("unroll")                                             \
        for (int _i = 0; _i < 2; ++_i) {                              \
            const float* _a0 = (aR) + _i * 16 * AST + (kk);           \
            (dst)[_i][0] = __float_as_uint(_a0[0]);                   \
            (dst)[_i][1] = __float_as_uint(_a0[8 * AST]);             \
            (dst)[_i][2] = __float_as_uint(_a0[4]);                   \
            (dst)[_i][3] = __float_as_uint(_a0[8 * AST + 4]);         \
        }                                                             \
    } while (0)

#define LOAD_BF8(dst, bR, kk)                                         \
    do {                                                              \
        _Pragma("unroll")                                             \
        for (int _j = 0; _j < 8; ++_j) {                              \
            const float* _b0 = (bR) + (kk) * BST + _j * 8;            \
            (dst)[_j][0] = __float_as_uint(_b0[0]);                   \
            (dst)[_j][1] = __float_as_uint(_b0[4 * BST]);             \
        }                                                             \
    } while (0)

#define LOAD_BF4(dst, bR, kk)                                         \
    do {                                                              \
        _Pragma("unroll")                                             \
        for (int _j = 0; _j < 4; ++_j) {                              \
            const float* _b0 = (bR) + (kk) * BST + _j * 8;            \
            (dst)[_j][0] = __float_as_uint(_b0[0]);                   \
            (dst)[_j][1] = __float_as_uint(_b0[4 * BST]);             \
        }                                                             \
    } while (0)

// ======================================================================
// Standard GEMM: 256 thr, 1 CTA/SM (255-reg budget), warp tile 32x64,
// explicit double-buffered fragments (LDS of step s+1 overlaps MMA of s).
// ======================================================================
template <int ROUND>
__global__ __launch_bounds__(256, 1)
void gemm_kernel(const float* __restrict__ A, const float* __restrict__ W,
                 const float* __restrict__ bias, float* __restrict__ C) {
    extern __shared__ char sm[];
    const uint32_t smb = smem_u32(sm);

    const int tid  = threadIdx.x;
    const int wid  = tid >> 5;
    const int lane = tid & 31;
    const int wm   = wid & 3;
    const int wn   = wid >> 2;
    const int g    = lane >> 2;
    const int tg   = lane & 3;
    const int bm   = blockIdx.y;
    const int bn   = blockIdx.x;

    const float* Abase = A + (size_t)(bm * TM) * NK;
    const float* Wbase = W + bn * 128;

    uint32_t sA[4], sB[4];
    const float* gA[4]; const float* gB[4];
#pragma unroll
    for (int it = 0; it < 4; ++it) {
        int p = tid + it * 256;
        int arow = p >> 3, acol = p & 7;
        int brow = p >> 5, bcol = p & 31;
        sA[it] = (uint32_t)((arow * AST + acol * 4) * 4);
        sB[it] = (uint32_t)(ABYT + (brow * BST + bcol * 4) * 4);
        gA[it] = Abase + (size_t)arow * NK + acol * 4;
        gB[it] = Wbase + (size_t)brow * NK + bcol * 4;
    }

    auto issue = [&](int kt) {
        const uint32_t sb = smb + (kt % STAGES) * STBYT;
        const int ko = kt * TKC;
        const size_t bo = (size_t)kt * TKC * NK;
#pragma unroll
        for (int it = 0; it < 4; ++it) cp16(sb + sA[it], gA[it] + ko);
#pragma unroll
        for (int it = 0; it < 4; ++it) cp16(sb + sB[it], gB[it] + bo);
    };

    float4 acc[2][8];
#pragma unroll
    for (int i = 0; i < 2; ++i)
#pragma unroll
        for (int j = 0; j < 8; ++j) acc[i][j] = make_float4(0.f, 0.f, 0.f, 0.f);

    issue(0); cp_commit();
    issue(1); cp_commit();

    const int arow0 = wm * 32 + g;
    const int ncol0 = wn * 64 + g;

    uint32_t af[2][2][4], bf[2][8][2];   // [buf][...]

    for (int kt = 0; kt < KT; ++kt) {
        cp_wait1();
        __syncthreads();
        if (kt + 2 < KT) issue(kt + 2);
        cp_commit();

        const float* As0 = (const float*)(sm + (kt % STAGES) * STBYT);
        const float* Bs0 = As0 + TM * AST;
        const float* aR = As0 + arow0 * AST + tg;
        const float* bR = Bs0 + tg * BST + ncol0;

        LOAD_AF(af[0], aR, 0);
        LOAD_BF8(bf[0], bR, 0);
#pragma unroll
        for (int s = 0; s < 4; ++s) {
            const int cur = s & 1, nxt = cur ^ 1;
            if (s < 3) {
                LOAD_AF(af[nxt], aR, (s + 1) * 8);
                LOAD_BF8(bf[nxt], bR, (s + 1) * 8);
            }
#pragma unroll
            for (int i = 0; i < 2; ++i)
#pragma unroll
                for (int j = 0; j < 8; ++j) mma_tf32(acc[i][j], af[cur][i], bf[cur][j]);
        }
    }

#pragma unroll
    for (int i = 0; i < 2; ++i) {
        int row = bm * TM + wm * 32 + i * 16 + g;
#pragma unroll
        for (int j = 0; j < 8; ++j) {
            int col = bn * 128 + wn * 64 + j * 8 + tg * 2;
            float b0 = bias[col], b1 = bias[col + 1];
            float v0 = acc[i][j].x + b0;
            float v1 = acc[i][j].y + b1;
            float v2 = acc[i][j].z + b0;
            float v3 = acc[i][j].w + b1;
            if (ROUND) {
                v0 = to_tf32(v0); v1 = to_tf32(v1);
                v2 = to_tf32(v2); v3 = to_tf32(v3);
            }
            size_t i0 = (size_t)row * NK + col;
            size_t i1 = (size_t)(row + 8) * NK + col;
            *reinterpret_cast<float2*>(&C[i0]) = make_float2(v0, v1);
            *reinterpret_cast<float2*>(&C[i1]) = make_float2(v2, v3);
        }
    }
}

// ======================================================================
// Fused gate GEMM: same 1-CTA + double-buffered fragment scheme.
// ======================================================================
__global__ __launch_bounds__(256, 1)
void gate_gemm(const float* __restrict__ V, const float* __restrict__ Wgx,
               const float* __restrict__ Wga, const float* __restrict__ bgx,
               const float* __restrict__ bga, const float* __restrict__ sp,
               float* __restrict__ aOut, float* __restrict__ sOut) {
    extern __shared__ char sm[];
    const uint32_t smb = smem_u32(sm);

    const int tid  = threadIdx.x;
    const int wid  = tid >> 5;
    const int lane = tid & 31;
    const int wm   = wid & 3;
    const int wn   = wid >> 2;
    const int g    = lane >> 2;
    const int tg   = lane & 3;
    const int bm   = blockIdx.y;
    const int bn   = blockIdx.x;

    const float* Abase = V + (size_t)(bm * TM) * NK;

    uint32_t sA[4], sB[4];
    const float* gA[4]; const float* gB[4];
#pragma unroll
    for (int it = 0; it < 4; ++it) {
        int p = tid + it * 256;
        int arow = p >> 3, acol = p & 7;
        int brow = p >> 5, bcol = p & 31;
        sA[it] = (uint32_t)((arow * AST + acol * 4) * 4);
        sB[it] = (uint32_t)(ABYT + (brow * BST + bcol * 4) * 4);
        gA[it] = Abase + (size_t)arow * NK + acol * 4;
        const float* wsrc = (bcol < 16) ? (Wgx + bn * 64 + bcol * 4)
                                        : (Wga + bn * 64 + (bcol - 16) * 4);
        gB[it] = wsrc + (size_t)brow * NK;
    }

    auto issue = [&](int kt) {
        const uint32_t sb = smb + (kt % STAGES) * STBYT;
        const int ko = kt * TKC;
        const size_t bo = (size_t)kt * TKC * NK;
#pragma unroll
        for (int it = 0; it < 4; ++it) cp16(sb + sA[it], gA[it] + ko);
#pragma unroll
        for (int it = 0; it < 4; ++it) cp16(sb + sB[it], gB[it] + bo);
    };

    float4 accX[2][4], accA[2][4];
#pragma unroll
    for (int i = 0; i < 2; ++i)
#pragma unroll
        for (int j = 0; j < 4; ++j) {
            accX[i][j] = make_float4(0.f, 0.f, 0.f, 0.f);
            accA[i][j] = make_float4(0.f, 0.f, 0.f, 0.f);
        }

    issue(0); cp_commit();
    issue(1); cp_commit();

    const int arow0 = wm * 32 + g;
    const int nX0 = wn * 32 + g;
    const int nA0 = 64 + wn * 32 + g;

    uint32_t af[2][2][4], bfX[2][4][2], bfA[2][4][2];

    for (int kt = 0; kt < KT; ++kt) {
        cp_wait1();
        __syncthreads();
        if (kt + 2 < KT) issue(kt + 2);
        cp_commit();

        const float* As0 = (const float*)(sm + (kt % STAGES) * STBYT);
        const float* Bs0 = As0 + TM * AST;
        const float* aR = As0 + arow0 * AST + tg;
        const float* bX = Bs0 + tg * BST + nX0;
        const float* bA = Bs0 + tg * BST + nA0;

        LOAD_AF(af[0], aR, 0);
        LOAD_BF4(bfX[0], bX, 0);
        LOAD_BF4(bfA[0], bA, 0);
#pragma unroll
        for (int s = 0; s < 4; ++s) {
            const int cur = s & 1, nxt = cur ^ 1;
            if (s < 3) {
                LOAD_AF(af[nxt], aR, (s + 1) * 8);
                LOAD_BF4(bfX[nxt], bX, (s + 1) * 8);
                LOAD_BF4(bfA[nxt], bA, (s + 1) * 8);
            }
#pragma unroll
            for (int i = 0; i < 2; ++i)
#pragma unroll
                for (int j = 0; j < 4; ++j) {
                    mma_tf32(accX[i][j], af[cur][i], bfX[cur][j]);
                    mma_tf32(accA[i][j], af[cur][i], bfA[cur][j]);
                }
        }
    }

#pragma unroll
    for (int i = 0; i < 2; ++i) {
        int row = bm * TM + wm * 32 + i * 16 + g;
#pragma unroll
        for (int j = 0; j < 4; ++j) {
            int col = bn * 64 + wn * 32 + j * 8 + tg * 2;
            float bx0 = bgx[col], bx1 = bgx[col + 1];
            float ba0 = bga[col], ba1 = bga[col + 1];
            float sp0 = sp[col],  sp1 = sp[col + 1];
            size_t i0 = (size_t)row * NK + col;
            size_t i1 = (size_t)(row + 8) * NK + col;
            float2 v0 = *reinterpret_cast<const float2*>(&V[i0]);
            float2 v1 = *reinterpret_cast<const float2*>(&V[i1]);

            float gx0 = fast_sigmoid(accX[i][j].x + bx0);
            float gx1 = fast_sigmoid(accX[i][j].y + bx1);
            float gx2 = fast_sigmoid(accX[i][j].z + bx0);
            float gx3 = fast_sigmoid(accX[i][j].w + bx1);
            float la0 = -8.0f * fast_sigmoid(accA[i][j].x + ba0) * sp0;
            float la1 = -8.0f * fast_sigmoid(accA[i][j].y + ba1) * sp1;
            float la2 = -8.0f * fast_sigmoid(accA[i][j].z + ba0) * sp0;
            float la3 = -8.0f * fast_sigmoid(accA[i][j].w + ba1) * sp1;

            float a0 = expf(la0), a1 = expf(la1), a2 = expf(la2), a3 = expf(la3);
            float s0 = sqrtf(1.0f - expf(2.0f * la0)) * gx0 * v0.x;
            float s1 = sqrtf(1.0f - expf(2.0f * la1)) * gx1 * v0.y;
            float s2 = sqrtf(1.0f - expf(2.0f * la2)) * gx2 * v1.x;
            float s3 = sqrtf(1.0f - expf(2.0f * la3)) * gx3 * v1.y;

            *reinterpret_cast<float2*>(&aOut[i0]) = make_float2(a0, a1);
            *reinterpret_cast<float2*>(&aOut[i1]) = make_float2(a2, a3);
            *reinterpret_cast<float2*>(&sOut[i0]) = make_float2(s0, s1);
            *reinterpret_cast<float2*>(&sOut[i1]) = make_float2(s2, s3);
        }
    }
}

// ======================================================================
// Fused output GEMM: 1 CTA/SM + double-buffered fragments, K=2048 concat.
// out = u@Wf2 + gx@Wb2 + biases + x
// ======================================================================
__global__ __launch_bounds__(256, 1)
void out_gemm(const float* __restrict__ A1, const float* __restrict__ A2,
              const float* __restrict__ W1, const float* __restrict__ W2,
              const float* __restrict__ b1, const float* __restrict__ b2,
              const float* __restrict__ X, float* __restrict__ C) {
    extern __shared__ char sm[];
    const uint32_t smb = smem_u32(sm);

    const int tid  = threadIdx.x;
    const int wid  = tid >> 5;
    const int lane = tid & 31;
    const int wm   = wid & 3;
    const int wn   = wid >> 2;
    const int g    = lane >> 2;
    const int tg   = lane & 3;
    const int bm   = blockIdx.y;
    const int bn   = blockIdx.x;

    uint32_t sA[4], sB[4], aoff[4], boff[4];
#pragma unroll
    for (int it = 0; it < 4; ++it) {
        int p = tid + it * 256;
        int arow = p >> 3, acol = p & 7;
        int brow = p >> 5, bcol = p & 31;
        sA[it] = (uint32_t)((arow * AST + acol * 4) * 4);
        sB[it] = (uint32_t)(ABYT + (brow * BST + bcol * 4) * 4);
        aoff[it] = (uint32_t)(arow * NK + acol * 4);
        boff[it] = (uint32_t)(brow * NK + bcol * 4);
    }
    const size_t arowbase = (size_t)(bm * TM) * NK;

    auto issue = [&](int kt) {
        const uint32_t sb = smb + (kt % STAGES) * STBYT;
        const int k2 = (kt < KT) ? kt : kt - KT;
        const float* Ab = ((kt < KT) ? A1 : A2) + arowbase + k2 * TKC;
        const float* Wb = ((kt < KT) ? W1 : W2) + bn * 128 + (size_t)k2 * TKC * NK;
#pragma unroll
        for (int it = 0; it < 4; ++it) cp16(sb + sA[it], Ab + aoff[it]);
#pragma unroll
        for (int it = 0; it < 4; ++it) cp16(sb + sB[it], Wb + boff[it]);
    };

    float4 acc[2][8];
#pragma unroll
    for (int i = 0; i < 2; ++i)
#pragma unroll
        for (int j = 0; j < 8; ++j) acc[i][j] = make_float4(0.f, 0.f, 0.f, 0.f);

    issue(0); cp_commit();
    issue(1); cp_commit();

    const int arow0 = wm * 32 + g;
    const int ncol0 = wn * 64 + g;

    uint32_t af[2][2][4], bf[2][8][2];

    for (int kt = 0; kt < 2 * KT; ++kt) {
        cp_wait1();
        __syncthreads();
        if (kt + 2 < 2 * KT) issue(kt + 2);
        cp_commit();

        const float* As0 = (const float*)(sm + (kt % STAGES) * STBYT);
        const float* Bs0 = As0 + TM * AST;
        const float* aR = As0 + arow0 * AST + tg;
        const float* bR = Bs0 + tg * BST + ncol0;

        LOAD_AF(af[0], aR, 0);
        LOAD_BF8(bf[0], bR, 0);
#pragma unroll
        for (int s = 0; s < 4; ++s) {
            const int cur = s & 1, nxt = cur ^ 1;
            if (s < 3) {
                LOAD_AF(af[nxt], aR, (s + 1) * 8);
                LOAD_BF8(bf[nxt], bR, (s + 1) * 8);
            }
#pragma unroll
            for (int i = 0; i < 2; ++i)
#pragma unroll
                for (int j = 0; j < 8; ++j) mma_tf32(acc[i][j], af[cur][i], bf[cur][j]);
        }
    }

#pragma unroll
    for (int i = 0; i < 2; ++i) {
        int row = bm * TM + wm * 32 + i * 16 + g;
#pragma unroll
        for (int j = 0; j < 8; ++j) {
            int col = bn * 128 + wn * 64 + j * 8 + tg * 2;
            float c0 = b1[col] + b2[col];
            float c1 = b1[col + 1] + b2[col + 1];
            size_t i0 = (size_t)row * NK + col;
            size_t i1 = (size_t)(row + 8) * NK + col;
            float2 x0 = *reinterpret_cast<const float2*>(&X[i0]);
            float2 x1 = *reinterpret_cast<const float2*>(&X[i1]);
            float v0 = acc[i][j].x + c0 + x0.x;
            float v1 = acc[i][j].y + c1 + x0.y;
            float v2 = acc[i][j].z + c0 + x1.x;
            float v3 = acc[i][j].w + c1 + x1.y;
            *reinterpret_cast<float2*>(&C[i0]) = make_float2(v0, v1);
            *reinterpret_cast<float2*>(&C[i1]) = make_float2(v2, v3);
        }
    }
}

// ---------------- launch ----------------
extern "C" void kernel_launch(void* const* d_in, const int* in_sizes, int n_in,
                              void* d_out, int out_size) {
    (void)in_sizes; (void)n_in; (void)out_size;
    const float* x       = (const float*)d_in[0];
    const float* a_fwd   = (const float*)d_in[1];
    const float* Wf1     = (const float*)d_in[2];
    const float* bf1     = (const float*)d_in[3];
    const float* Wf2     = (const float*)d_in[4];
    const float* bf2     = (const float*)d_in[5];
    const float* Wbx     = (const float*)d_in[6];
    const float* bbx     = (const float*)d_in[7];
    const float* Wgx     = (const float*)d_in[8];
    const float* bgx     = (const float*)d_in[9];
    const float* Wga     = (const float*)d_in[10];
    const float* bga     = (const float*)d_in[11];
    const float* a_param = (const float*)d_in[12];
    const float* Wb2     = (const float*)d_in[13];
    const float* bb2     = (const float*)d_in[14];
    float* out = (float*)d_out;

    float *xg, *u, *v, *gx, *ga, *wt, *sp;
    float *e1, *P1, *c1, *e2, *P2, *c2;
    cudaGetSymbolAddress((void**)&xg, g_xg);
    cudaGetSymbolAddress((void**)&u,  g_u);
    cudaGetSymbolAddress((void**)&v,  g_v);
    cudaGetSymbolAddress((void**)&gx, g_gx);
    cudaGetSymbolAddress((void**)&ga, g_ga);
    cudaGetSymbolAddress((void**)&wt, g_wt);
    cudaGetSymbolAddress((void**)&sp, g_sp);
    cudaGetSymbolAddress((void**)&e1, g_e1);
    cudaGetSymbolAddress((void**)&P1, g_P1);
    cudaGetSymbolAddress((void**)&c1, g_c1);
    cudaGetSymbolAddress((void**)&e2, g_e2);
    cudaGetSymbolAddress((void**)&P2, g_P2);
    cudaGetSymbolAddress((void**)&c2, g_c2);

    cudaFuncSetAttribute(gemm_kernel<0>, cudaFuncAttributeMaxDynamicSharedMemorySize, SMEM_REQ);
    cudaFuncSetAttribute(gemm_kernel<1>, cudaFuncAttributeMaxDynamicSharedMemorySize, SMEM_REQ);
    cudaFuncSetAttribute(gate_gemm,      cudaFuncAttributeMaxDynamicSharedMemorySize, SMEM_REQ);
    cudaFuncSetAttribute(out_gemm,       cudaFuncAttributeMaxDynamicSharedMemorySize, SMEM_REQ);

    dim3 rwgrid(NK * NK / 4 / 256, 6);
    roundw_all<<<rwgrid, 256>>>(Wf1, Wbx, Wgx, Wga, Wf2, Wb2, wt);
    softplus_prep<<<1, DD>>>(a_param, sp);

    const int EW_BLOCKS = (NELEM / 4) / 256;
    gelu_kernel<<<EW_BLOCKS, 256>>>(x, xg);

    dim3 ggrid(8, 256);
    dim3 ggrid2(16, 256);
    gemm_kernel<0><<<ggrid, 256, SMEM_REQ>>>(xg, wt + 0ull*NK*NK, bf1, u);
    gemm_kernel<1><<<ggrid, 256, SMEM_REQ>>>(xg, wt + 1ull*NK*NK, bbx, v);
    gate_gemm<<<ggrid2, 256, SMEM_REQ>>>(v, wt + 2ull*NK*NK, wt + 3ull*NK*NK,
                                         bgx, bga, sp, ga, gx);

    dim3 s1grid(BB * NCH, 2), s2grid(BB, 2);
    scan_p1<<<s1grid, DD>>>(u, a_fwd, gx, ga, e1, P1, e2, P2);
    scan_p2<<<s2grid, DD>>>(e1, P1, c1, e2, P2, c2);
    scan_p3<<<s1grid, DD>>>(u, a_fwd, c1, gx, ga, c2);

    out_gemm<<<ggrid, 256, SMEM_REQ>>>(u, gx, wt + 4ull*NK*NK, wt + 5ull*NK*NK,
                                       bf2, bb2, x, out);
}

// round 15
// speedup vs baseline: 1.2209x; 1.2209x over previous
#include <cuda_runtime.h>
#include <cstdint>

#define BB 8
#define SS 4096
#define DD 1024
#define MTOT (BB*SS)            // 32768
#define NELEM (MTOT*DD)
#define NK 1024

#define NCH 32
#define CHL 128                 // SS/NCH

// ---- GEMM tiling (256-thread CTA, warp tile 32x64, proven shape) ----
#define TM 128
#define TKC 32
#define KT (NK/TKC)             // 32
#define STAGES 3
#define AST 36
#define BST 136
#define ABYT (TM*AST*4)         // 18432
#define BBYT (TKC*BST*4)        // 17408
#define STBYT (ABYT+BBYT)       // 35840
#define SMEM_REQ (STAGES*STBYT) // 107520

// ---------------- scratch ----------------
__device__ float g_xg[NELEM];   // gelu(x)
__device__ float g_u [NELEM];
__device__ float g_v [NELEM];
__device__ float g_gx[NELEM];   // scaled_in -> bwd states
__device__ float g_ga[NELEM];   // a (decay)
__device__ float g_wt[6*NK*NK]; // tf32-rounded weights [K][N]
__device__ float g_sp[DD];      // softplus(a_param)
__device__ float g_e1[BB*NCH*DD];
__device__ float g_P1[BB*NCH*DD];
__device__ float g_c1[BB*NCH*DD];
__device__ float g_e2[BB*NCH*DD];
__device__ float g_P2[BB*NCH*DD];
__device__ float g_c2[BB*NCH*DD];

// ---------------- helpers ----------------
__device__ __forceinline__ float to_tf32(float x) {
    float r; asm("cvt.rna.tf32.f32 %0, %1;" : "=f"(r) : "f"(x)); return r;
}
__device__ __forceinline__ uint32_t smem_u32(const void* p) {
    uint32_t a;
    asm("{ .reg .u64 t; cvta.to.shared.u64 t, %1; cvt.u32.u64 %0, t; }" : "=r"(a) : "l"(p));
    return a;
}
__device__ __forceinline__ void cp16(uint32_t saddr, const void* gaddr) {
    asm volatile("cp.async.cg.shared.global [%0], [%1], 16;" :: "r"(saddr), "l"(gaddr));
}
__device__ __forceinline__ void cp_commit() {
    asm volatile("cp.async.commit_group;" ::: "memory");
}
__device__ __forceinline__ void cp_wait1() {
    asm volatile("cp.async.wait_group 1;" ::: "memory");
}
__device__ __forceinline__ void mma_tf32(float4& c, const uint32_t* a, const uint32_t* b) {
    asm volatile(
        "mma.sync.aligned.m16n8k8.row.col.f32.tf32.tf32.f32 "
        "{%0,%1,%2,%3},{%4,%5,%6,%7},{%8,%9},{%0,%1,%2,%3};\n"
        : "+f"(c.x), "+f"(c.y), "+f"(c.z), "+f"(c.w)
        : "r"(a[0]), "r"(a[1]), "r"(a[2]), "r"(a[3]), "r"(b[0]), "r"(b[1]));
}
__device__ __forceinline__ float fast_sigmoid(float x) {
    return 1.0f / (1.0f + __expf(-x));
}

// ---------------- weight prep (+ softplus folded in) ----------------
__global__ void roundw_all(const float* __restrict__ w0, const float* __restrict__ w1,
                           const float* __restrict__ w2, const float* __restrict__ w3,
                           const float* __restrict__ w4, const float* __restrict__ w5,
                           const float* __restrict__ ap,
                           float* __restrict__ dst, float* __restrict__ sp) {
    if (blockIdx.y == 6) {
        if (blockIdx.x == 0) {
            int d = threadIdx.x;          // 256 threads -> 4 elems each
#pragma unroll
            for (int k = 0; k < 4; ++k) {
                int idx = d + k * 256;
                sp[idx] = log1pf(expf(ap[idx]));
            }
        }
        return;
    }
    const float* srcs[6] = {w0, w1, w2, w3, w4, w5};
    const float* src = srcs[blockIdx.y];
    float* d = dst + (size_t)blockIdx.y * NK * NK;
    int i = blockIdx.x * blockDim.x + threadIdx.x;
    float4 v = reinterpret_cast<const float4*>(src)[i];
    v.x = to_tf32(v.x); v.y = to_tf32(v.y); v.z = to_tf32(v.z); v.w = to_tf32(v.w);
    reinterpret_cast<float4*>(d)[i] = v;
}

// ---------------- gelu ----------------
__global__ void gelu_kernel(const float* __restrict__ x, float* __restrict__ y) {
    int i = blockIdx.x * blockDim.x + threadIdx.x;
    float4 v = reinterpret_cast<const float4*>(x)[i];
    float* p = &v.x;
    float4 r; float* q = &r.x;
#pragma unroll
    for (int k = 0; k < 4; ++k) {
        float t = p[k];
        float inner = 0.7978845608028654f * (t + 0.044715f * t * t * t);
        q[k] = to_tf32(t * fast_sigmoid(2.0f * inner));
    }
    reinterpret_cast<float4*>(y)[i] = r;
}

// ---------------- merged chunked scans ----------------
__global__ void scan_p1(const float* __restrict__ u, const float* __restrict__ afwd,
                        const float* __restrict__ s, const float* __restrict__ a,
                        float* __restrict__ e1, float* __restrict__ P1,
                        float* __restrict__ e2, float* __restrict__ P2) {
    int d = threadIdx.x, bc = blockIdx.x;
    size_t base = (size_t)bc * CHL * DD + d;
    if (blockIdx.y == 0) {
        float av = afwd[d];
        float h = 0.f;
#pragma unroll 4
        for (int t = 0; t < CHL; ++t) h = fmaf(av, h, u[base + (size_t)t * DD]);
        float p = av;
#pragma unroll
        for (int i = 0; i < 7; ++i) p *= p;     // a^128
        e1[bc * DD + d] = h; P1[bc * DD + d] = p;
    } else {
        float h = 0.f, p = 1.f;
#pragma unroll 4
        for (int t = CHL - 1; t >= 0; --t) {
            size_t i = base + (size_t)t * DD;
            float av = a[i];
            h = fmaf(av, h, s[i]);
            p *= av;
        }
        e2[bc * DD + d] = h; P2[bc * DD + d] = p;
    }
}

__global__ void scan_p2(const float* __restrict__ e1, const float* __restrict__ P1,
                        float* __restrict__ c1,
                        const float* __restrict__ e2, const float* __restrict__ P2,
                        float* __restrict__ c2) {
    int gidx = blockIdx.x * blockDim.x + threadIdx.x;
    int b = gidx >> 10, d = gidx & 1023;
    if (blockIdx.y == 0) {
        float acc = 0.f;
        for (int c = 0; c < NCH; ++c) {
            size_t i = (size_t)(b * NCH + c) * DD + d;
            c1[i] = acc;
            acc = e1[i] + P1[i] * acc;
        }
    } else {
        float acc = 0.f;
        for (int c = NCH - 1; c >= 0; --c) {
            size_t i = (size_t)(b * NCH + c) * DD + d;
            c2[i] = acc;
            acc = e2[i] + P2[i] * acc;
        }
    }
}

__global__ void scan_p3(float* __restrict__ u, const float* __restrict__ afwd,
                        const float* __restrict__ c1,
                        float* __restrict__ s, const float* __restrict__ a,
                        const float* __restrict__ c2) {
    int d = threadIdx.x, bc = blockIdx.x;
    size_t base = (size_t)bc * CHL * DD + d;
    if (blockIdx.y == 0) {
        float av = afwd[d];
        float h = c1[bc * DD + d];
#pragma unroll 4
        for (int t = 0; t < CHL; ++t) {
            size_t i = base + (size_t)t * DD;
            h = fmaf(av, h, u[i]);
            u[i] = to_tf32(h);
        }
    } else {
        float h = c2[bc * DD + d];
#pragma unroll 4
        for (int t = CHL - 1; t >= 0; --t) {
            size_t i = base + (size_t)t * DD;
            h = fmaf(a[i], h, s[i]);
            s[i] = to_tf32(h);
        }
    }
}

// ======================================================================
// in2_gemm: u-GEMM and v-GEMM merged into ONE launch (independent work).
// grid(16,256): bn<8 -> Wf1/bf1 -> u (no round); bn>=8 -> Wbx/bbx -> v (round).
// Mainloop identical to the proven R12 shape (2 CTA/SM, warp tile 32x64).
// ======================================================================
__global__ __launch_bounds__(256, 2)
void in2_gemm(const float* __restrict__ A,
              const float* __restrict__ W0, const float* __restrict__ W1,
              const float* __restrict__ b0, const float* __restrict__ b1v,
              float* __restrict__ U, float* __restrict__ V) {
    extern __shared__ char sm[];
    const uint32_t smb = smem_u32(sm);

    const int tid  = threadIdx.x;
    const int wid  = tid >> 5;
    const int lane = tid & 31;
    const int wm   = wid & 3;
    const int wn   = wid >> 2;
    const int g    = lane >> 2;
    const int tg   = lane & 3;
    const int bm   = blockIdx.y;
    const int sel  = (blockIdx.x >> 3);          // 0 -> u, 1 -> v
    const int bn   = blockIdx.x & 7;

    const float* W    = sel ? W1  : W0;
    const float* bias = sel ? b1v : b0;
    float* C          = sel ? V   : U;

    const float* Abase = A + (size_t)(bm * TM) * NK;
    const float* Wbase = W + bn * 128;

    uint32_t sA[4], sB[4];
    const float* gA[4]; const float* gB[4];
#pragma unroll
    for (int it = 0; it < 4; ++it) {
        int p = tid + it * 256;
        int arow = p >> 3, acol = p & 7;
        int brow = p >> 5, bcol = p & 31;
        sA[it] = (uint32_t)((arow * AST + acol * 4) * 4);
        sB[it] = (uint32_t)(ABYT + (brow * BST + bcol * 4) * 4);
        gA[it] = Abase + (size_t)arow * NK + acol * 4;
        gB[it] = Wbase + (size_t)brow * NK + bcol * 4;
    }

    auto issue = [&](int kt) {
        const uint32_t sb = smb + (kt % STAGES) * STBYT;
        const int ko = kt * TKC;
        const size_t bo = (size_t)kt * TKC * NK;
#pragma unroll
        for (int it = 0; it < 4; ++it) cp16(sb + sA[it], gA[it] + ko);
#pragma unroll
        for (int it = 0; it < 4; ++it) cp16(sb + sB[it], gB[it] + bo);
    };

    float4 acc[2][8];
#pragma unroll
    for (int i = 0; i < 2; ++i)
#pragma unroll
        for (int j = 0; j < 8; ++j) acc[i][j] = make_float4(0.f, 0.f, 0.f, 0.f);

    issue(0); cp_commit();
    issue(1); cp_commit();

    const int arow0 = wm * 32 + g;
    const int ncol0 = wn * 64 + g;

    for (int kt = 0; kt < KT; ++kt) {
        cp_wait1();
        __syncthreads();
        if (kt + 2 < KT) issue(kt + 2);
        cp_commit();

        const float* As0 = (const float*)(sm + (kt % STAGES) * STBYT);
        const float* Bs0 = As0 + TM * AST;
        const float* aR = As0 + arow0 * AST + tg;
        const float* bR = Bs0 + tg * BST + ncol0;

#pragma unroll
        for (int kk = 0; kk < TKC; kk += 8) {
            uint32_t af[2][4], bf[8][2];
#pragma unroll
            for (int i = 0; i < 2; ++i) {
                const float* a0 = aR + i * 16 * AST + kk;
                af[i][0] = __float_as_uint(a0[0]);
                af[i][1] = __float_as_uint(a0[8 * AST]);
                af[i][2] = __float_as_uint(a0[4]);
                af[i][3] = __float_as_uint(a0[8 * AST + 4]);
            }
#pragma unroll
            for (int j = 0; j < 8; ++j) {
                const float* b0 = bR + kk * BST + j * 8;
                bf[j][0] = __float_as_uint(b0[0]);
                bf[j][1] = __float_as_uint(b0[4 * BST]);
            }
#pragma unroll
            for (int i = 0; i < 2; ++i)
#pragma unroll
                for (int j = 0; j < 8; ++j) mma_tf32(acc[i][j], af[i], bf[j]);
        }
    }

#pragma unroll
    for (int i = 0; i < 2; ++i) {
        int row = bm * TM + wm * 32 + i * 16 + g;
#pragma unroll
        for (int j = 0; j < 8; ++j) {
            int col = bn * 128 + wn * 64 + j * 8 + tg * 2;
            float b0 = bias[col], b1 = bias[col + 1];
            float v0 = acc[i][j].x + b0;
            float v1 = acc[i][j].y + b1;
            float v2 = acc[i][j].z + b0;
            float v3 = acc[i][j].w + b1;
            if (sel) {
                v0 = to_tf32(v0); v1 = to_tf32(v1);
                v2 = to_tf32(v2); v3 = to_tf32(v3);
            }
            size_t i0 = (size_t)row * NK + col;
            size_t i1 = (size_t)(row + 8) * NK + col;
            *reinterpret_cast<float2*>(&C[i0]) = make_float2(v0, v1);
            *reinterpret_cast<float2*>(&C[i1]) = make_float2(v2, v3);
        }
    }
}

// ======================================================================
// Fused gate GEMM (proven R9/R12)
// ======================================================================
__global__ __launch_bounds__(256, 2)
void gate_gemm(const float* __restrict__ V, const float* __restrict__ Wgx,
               const float* __restrict__ Wga, const float* __restrict__ bgx,
               const float* __restrict__ bga, const float* __restrict__ sp,
               float* __restrict__ aOut, float* __restrict__ sOut) {
    extern __shared__ char sm[];
    const uint32_t smb = smem_u32(sm);

    const int tid  = threadIdx.x;
    const int wid  = tid >> 5;
    const int lane = tid & 31;
    const int wm   = wid & 3;
    const int wn   = wid >> 2;
    const int g    = lane >> 2;
    const int tg   = lane & 3;
    const int bm   = blockIdx.y;
    const int bn   = blockIdx.x;

    const float* Abase = V + (size_t)(bm * TM) * NK;

    uint32_t sA[4], sB[4];
    const float* gA[4]; const float* gB[4];
#pragma unroll
    for (int it = 0; it < 4; ++it) {
        int p = tid + it * 256;
        int arow = p >> 3, acol = p & 7;
        int brow = p >> 5, bcol = p & 31;
        sA[it] = (uint32_t)((arow * AST + acol * 4) * 4);
        sB[it] = (uint32_t)(ABYT + (brow * BST + bcol * 4) * 4);
        gA[it] = Abase + (size_t)arow * NK + acol * 4;
        const float* wsrc = (bcol < 16) ? (Wgx + bn * 64 + bcol * 4)
                                        : (Wga + bn * 64 + (bcol - 16) * 4);
        gB[it] = wsrc + (size_t)brow * NK;
    }

    auto issue = [&](int kt) {
        const uint32_t sb = smb + (kt % STAGES) * STBYT;
        const int ko = kt * TKC;
        const size_t bo = (size_t)kt * TKC * NK;
#pragma unroll
        for (int it = 0; it < 4; ++it) cp16(sb + sA[it], gA[it] + ko);
#pragma unroll
        for (int it = 0; it < 4; ++it) cp16(sb + sB[it], gB[it] + bo);
    };

    float4 accX[2][4], accA[2][4];
#pragma unroll
    for (int i = 0; i < 2; ++i)
#pragma unroll
        for (int j = 0; j < 4; ++j) {
            accX[i][j] = make_float4(0.f, 0.f, 0.f, 0.f);
            accA[i][j] = make_float4(0.f, 0.f, 0.f, 0.f);
        }

    issue(0); cp_commit();
    issue(1); cp_commit();

    const int arow0 = wm * 32 + g;
    const int nX0 = wn * 32 + g;
    const int nA0 = 64 + wn * 32 + g;

    for (int kt = 0; kt < KT; ++kt) {
        cp_wait1();
        __syncthreads();
        if (kt + 2 < KT) issue(kt + 2);
        cp_commit();

        const float* As0 = (const float*)(sm + (kt % STAGES) * STBYT);
        const float* Bs0 = As0 + TM * AST;
        const float* aR = As0 + arow0 * AST + tg;
        const float* bX = Bs0 + tg * BST + nX0;
        const float* bA = Bs0 + tg * BST + nA0;

#pragma unroll
        for (int kk = 0; kk < TKC; kk += 8) {
            uint32_t af[2][4], bfX[4][2], bfA[4][2];
#pragma unroll
            for (int i = 0; i < 2; ++i) {
                const float* a0 = aR + i * 16 * AST + kk;
                af[i][0] = __float_as_uint(a0[0]);
                af[i][1] = __float_as_uint(a0[8 * AST]);
                af[i][2] = __float_as_uint(a0[4]);
                af[i][3] = __float_as_uint(a0[8 * AST + 4]);
            }
#pragma unroll
            for (int j = 0; j < 4; ++j) {
                const float* b0 = bX + kk * BST + j * 8;
                bfX[j][0] = __float_as_uint(b0[0]);
                bfX[j][1] = __float_as_uint(b0[4 * BST]);
                const float* b1 = bA + kk * BST + j * 8;
                bfA[j][0] = __float_as_uint(b1[0]);
                bfA[j][1] = __float_as_uint(b1[4 * BST]);
            }
#pragma unroll
            for (int i = 0; i < 2; ++i)
#pragma unroll
                for (int j = 0; j < 4; ++j) {
                    mma_tf32(accX[i][j], af[i], bfX[j]);
                    mma_tf32(accA[i][j], af[i], bfA[j]);
                }
        }
    }

#pragma unroll
    for (int i = 0; i < 2; ++i) {
        int row = bm * TM + wm * 32 + i * 16 + g;
#pragma unroll
        for (int j = 0; j < 4; ++j) {
            int col = bn * 64 + wn * 32 + j * 8 + tg * 2;
            float bx0 = bgx[col], bx1 = bgx[col + 1];
            float ba0 = bga[col], ba1 = bga[col + 1];
            float sp0 = sp[col],  sp1 = sp[col + 1];
            size_t i0 = (size_t)row * NK + col;
            size_t i1 = (size_t)(row + 8) * NK + col;
            float2 v0 = *reinterpret_cast<const float2*>(&V[i0]);
            float2 v1 = *reinterpret_cast<const float2*>(&V[i1]);

            float gx0 = fast_sigmoid(accX[i][j].x + bx0);
            float gx1 = fast_sigmoid(accX[i][j].y + bx1);
            float gx2 = fast_sigmoid(accX[i][j].z + bx0);
            float gx3 = fast_sigmoid(accX[i][j].w + bx1);
            float la0 = -8.0f * fast_sigmoid(accA[i][j].x + ba0) * sp0;
            float la1 = -8.0f * fast_sigmoid(accA[i][j].y + ba1) * sp1;
            float la2 = -8.0f * fast_sigmoid(accA[i][j].z + ba0) * sp0;
            float la3 = -8.0f * fast_sigmoid(accA[i][j].w + ba1) * sp1;

            float a0 = expf(la0), a1 = expf(la1), a2 = expf(la2), a3 = expf(la3);
            float s0 = sqrtf(1.0f - expf(2.0f * la0)) * gx0 * v0.x;
            float s1 = sqrtf(1.0f - expf(2.0f * la1)) * gx1 * v0.y;
            float s2 = sqrtf(1.0f - expf(2.0f * la2)) * gx2 * v1.x;
            float s3 = sqrtf(1.0f - expf(2.0f * la3)) * gx3 * v1.y;

            *reinterpret_cast<float2*>(&aOut[i0]) = make_float2(a0, a1);
            *reinterpret_cast<float2*>(&aOut[i1]) = make_float2(a2, a3);
            *reinterpret_cast<float2*>(&sOut[i0]) = make_float2(s0, s1);
            *reinterpret_cast<float2*>(&sOut[i1]) = make_float2(s2, s3);
        }
    }
}

// ======================================================================
// Fused output GEMM (proven R9/R12): out = u@Wf2 + gx@Wb2 + biases + x
// ======================================================================
__global__ __launch_bounds__(256, 2)
void out_gemm(const float* __restrict__ A1, const float* __restrict__ A2,
              const float* __restrict__ W1, const float* __restrict__ W2,
              const float* __restrict__ b1, const float* __restrict__ b2,
              const float* __restrict__ X, float* __restrict__ C) {
    extern __shared__ char sm[];
    const uint32_t smb = smem_u32(sm);

    const int tid  = threadIdx.x;
    const int wid  = tid >> 5;
    const int lane = tid & 31;
    const int wm   = wid & 3;
    const int wn   = wid >> 2;
    const int g    = lane >> 2;
    const int tg   = lane & 3;
    const int bm   = blockIdx.y;
    const int bn   = blockIdx.x;

    uint32_t sA[4], sB[4], aoff[4], boff[4];
#pragma unroll
    for (int it = 0; it < 4; ++it) {
        int p = tid + it * 256;
        int arow = p >> 3, acol = p & 7;
        int brow = p >> 5, bcol = p & 31;
        sA[it] = (uint32_t)((arow * AST + acol * 4) * 4);
        sB[it] = (uint32_t)(ABYT + (brow * BST + bcol * 4) * 4);
        aoff[it] = (uint32_t)(arow * NK + acol * 4);
        boff[it] = (uint32_t)(brow * NK + bcol * 4);
    }
    const size_t arowbase = (size_t)(bm * TM) * NK;

    auto issue = [&](int kt) {
        const uint32_t sb = smb + (kt % STAGES) * STBYT;
        const int k2 = (kt < KT) ? kt : kt - KT;
        const float* Ab = ((kt < KT) ? A1 : A2) + arowbase + k2 * TKC;
        const float* Wb = ((kt < KT) ? W1 : W2) + bn * 128 + (size_t)k2 * TKC * NK;
#pragma unroll
        for (int it = 0; it < 4; ++it) cp16(sb + sA[it], Ab + aoff[it]);
#pragma unroll
        for (int it = 0; it < 4; ++it) cp16(sb + sB[it], Wb + boff[it]);
    };

    float4 acc[2][8];
#pragma unroll
    for (int i = 0; i < 2; ++i)
#pragma unroll
        for (int j = 0; j < 8; ++j) acc[i][j] = make_float4(0.f, 0.f, 0.f, 0.f);

    issue(0); cp_commit();
    issue(1); cp_commit();

    const int arow0 = wm * 32 + g;
    const int ncol0 = wn * 64 + g;

    for (int kt = 0; kt < 2 * KT; ++kt) {
        cp_wait1();
        __syncthreads();
        if (kt + 2 < 2 * KT) issue(kt + 2);
        cp_commit();

        const float* As0 = (const float*)(sm + (kt % STAGES) * STBYT);
        const float* Bs0 = As0 + TM * AST;
        const float* aR = As0 + arow0 * AST + tg;
        const float* bR = Bs0 + tg * BST + ncol0;

#pragma unroll
        for (int kk = 0; kk < TKC; kk += 8) {
            uint32_t af[2][4], bf[8][2];
#pragma unroll
            for (int i = 0; i < 2; ++i) {
                const float* a0 = aR + i * 16 * AST + kk;
                af[i][0] = __float_as_uint(a0[0]);
                af[i][1] = __float_as_uint(a0[8 * AST]);
                af[i][2] = __float_as_uint(a0[4]);
                af[i][3] = __float_as_uint(a0[8 * AST + 4]);
            }
#pragma unroll
            for (int j = 0; j < 8; ++j) {
                const float* b0 = bR + kk * BST + j * 8;
                bf[j][0] = __float_as_uint(b0[0]);
                bf[j][1] = __float_as_uint(b0[4 * BST]);
            }
#pragma unroll
            for (int i = 0; i < 2; ++i)
#pragma unroll
                for (int j = 0; j < 8; ++j) mma_tf32(acc[i][j], af[i], bf[j]);
        }
    }

#pragma unroll
    for (int i = 0; i < 2; ++i) {
        int row = bm * TM + wm * 32 + i * 16 + g;
#pragma unroll
        for (int j = 0; j < 8; ++j) {
            int col = bn * 128 + wn * 64 + j * 8 + tg * 2;
            float c0 = b1[col] + b2[col];
            float c1 = b1[col + 1] + b2[col + 1];
            size_t i0 = (size_t)row * NK + col;
            size_t i1 = (size_t)(row + 8) * NK + col;
            float2 x0 = *reinterpret_cast<const float2*>(&X[i0]);
            float2 x1 = *reinterpret_cast<const float2*>(&X[i1]);
            float v0 = acc[i][j].x + c0 + x0.x;
            float v1 = acc[i][j].y + c1 + x0.y;
            float v2 = acc[i][j].z + c0 + x1.x;
            float v3 = acc[i][j].w + c1 + x1.y;
            *reinterpret_cast<float2*>(&C[i0]) = make_float2(v0, v1);
            *reinterpret_cast<float2*>(&C[i1]) = make_float2(v2, v3);
        }
    }
}

// ---------------- launch ----------------
extern "C" void kernel_launch(void* const* d_in, const int* in_sizes, int n_in,
                              void* d_out, int out_size) {
    (void)in_sizes; (void)n_in; (void)out_size;
    const float* x       = (const float*)d_in[0];
    const float* a_fwd   = (const float*)d_in[1];
    const float* Wf1     = (const float*)d_in[2];
    const float* bf1     = (const float*)d_in[3];
    const float* Wf2     = (const float*)d_in[4];
    const float* bf2     = (const float*)d_in[5];
    const float* Wbx     = (const float*)d_in[6];
    const float* bbx     = (const float*)d_in[7];
    const float* Wgx     = (const float*)d_in[8];
    const float* bgx     = (const float*)d_in[9];
    const float* Wga     = (const float*)d_in[10];
    const float* bga     = (const float*)d_in[11];
    const float* a_param = (const float*)d_in[12];
    const float* Wb2     = (const float*)d_in[13];
    const float* bb2     = (const float*)d_in[14];
    float* out = (float*)d_out;

    float *xg, *u, *v, *gx, *ga, *wt, *sp;
    float *e1, *P1, *c1, *e2, *P2, *c2;
    cudaGetSymbolAddress((void**)&xg, g_xg);
    cudaGetSymbolAddress((void**)&u,  g_u);
    cudaGetSymbolAddress((void**)&v,  g_v);
    cudaGetSymbolAddress((void**)&gx, g_gx);
    cudaGetSymbolAddress((void**)&ga, g_ga);
    cudaGetSymbolAddress((void**)&wt, g_wt);
    cudaGetSymbolAddress((void**)&sp, g_sp);
    cudaGetSymbolAddress((void**)&e1, g_e1);
    cudaGetSymbolAddress((void**)&P1, g_P1);
    cudaGetSymbolAddress((void**)&c1, g_c1);
    cudaGetSymbolAddress((void**)&e2, g_e2);
    cudaGetSymbolAddress((void**)&P2, g_P2);
    cudaGetSymbolAddress((void**)&c2, g_c2);

    cudaFuncSetAttribute(in2_gemm,  cudaFuncAttributeMaxDynamicSharedMemorySize, SMEM_REQ);
    cudaFuncSetAttribute(gate_gemm, cudaFuncAttributeMaxDynamicSharedMemorySize, SMEM_REQ);
    cudaFuncSetAttribute(out_gemm,  cudaFuncAttributeMaxDynamicSharedMemorySize, SMEM_REQ);

    dim3 rwgrid(NK * NK / 4 / 256, 7);    // y=0..5 weights, y=6 softplus
    roundw_all<<<rwgrid, 256>>>(Wf1, Wbx, Wgx, Wga, Wf2, Wb2, a_param, wt, sp);

    const int EW_BLOCKS = (NELEM / 4) / 256;
    gelu_kernel<<<EW_BLOCKS, 256>>>(x, xg);

    dim3 ggrid2(16, 256);
    in2_gemm<<<ggrid2, 256, SMEM_REQ>>>(xg, wt + 0ull*NK*NK, wt + 1ull*NK*NK,
                                        bf1, bbx, u, v);
    gate_gemm<<<ggrid2, 256, SMEM_REQ>>>(v, wt + 2ull*NK*NK, wt + 3ull*NK*NK,
                                         bgx, bga, sp, ga, gx);

    dim3 s1grid(BB * NCH, 2), s2grid(BB, 2);
    scan_p1<<<s1grid, DD>>>(u, a_fwd, gx, ga, e1, P1, e2, P2);
    scan_p2<<<s2grid, DD>>>(e1, P1, c1, e2, P2, c2);
    scan_p3<<<s1grid, DD>>>(u, a_fwd, c1, gx, ga, c2);

    dim3 ggrid(8, 256);
    out_gemm<<<ggrid, 256, SMEM_REQ>>>(u, gx, wt + 4ull*NK*NK, wt + 5ull*NK*NK,
                                       bf2, bb2, x, out);
}